// round 13
// baseline (speedup 1.0000x reference)
#include <cuda_runtime.h>

#define NB 2
#define P  8192
#define HH 48
#define WW 48
#define RH 95
#define RW 95
#define QQ (RH*RW)          // 9025
#define NA_TOT (NB*P)       // 16384
#define NBQ_TOT (NB*QQ)     // 18050
#define TOT_PTS (NA_TOT + NBQ_TOT)  // 34434

#define NBINS 128
#define XMINF (-8.0f)
#define BWF   (0.125f)
#define INVBW (8.0f)
#define CAP   9600          // >= 9025 + 3*NBINS padding

#define BLK 128
#define CTA_A_PER (P/BLK)            // 64
#define CTA_B_PER ((QQ+BLK-1)/BLK)   // 71
#define KGRID (NB*CTA_A_PER + NB*CTA_B_PER)  // 270

// scratch (allocation-free rule: __device__ globals; zero-init; self-resetting)
__device__ float4 g_ptsM[NBQ_TOT];
__device__ float4 g_ptsP[NA_TOT];
__device__ int    g_hist[4][NBINS];
__device__ int    g_off[4][NBINS+1];   // padded bin offsets (multiples of 4)
__device__ int    g_cur[4][NBINS];     // padded scatter cursors
__device__ int    g_ccur[4][NBINS];    // compact scatter cursors
__device__ __align__(16) float g_bx[4][CAP];
__device__ __align__(16) float g_by[4][CAP];
__device__ __align__(16) float g_bz[4][CAP];
__device__ __align__(16) float g_bnw[4][CAP];   // -0.5|b|^2 ; sentinel -3e38 in pad slots
__device__ float g_cx[4][CAP];        // compact (dense) bin-sorted copy for a-side
__device__ float g_cy[4][CAP];
__device__ float g_cz[4][CAP];
__device__ float g_cw[4][CAP];        // +0.5|a|^2
__device__ int   g_coid[4][CAP];      // original index within cloud-batch
__device__ float g_minA[NA_TOT];
__device__ float g_minB[NBQ_TOT];
__device__ float g_fpart[KGRID];
__device__ int   g_done, g_done2;

// ---------------------------------------------------------------------------
// f32x2 packed helpers
// ---------------------------------------------------------------------------
__device__ __forceinline__ unsigned long long fma2(unsigned long long a,
                                                   unsigned long long b,
                                                   unsigned long long c)
{
    unsigned long long d;
    asm("fma.rn.f32x2 %0, %1, %2, %3;" : "=l"(d) : "l"(a), "l"(b), "l"(c));
    return d;
}
__device__ __forceinline__ unsigned long long pack2(float x, float y)
{
    unsigned long long r;
    asm("mov.b64 %0, {%1,%2};" : "=l"(r) : "f"(x), "f"(y));
    return r;
}
__device__ __forceinline__ float2 u2f(unsigned long long v)
{
    float2 r;
    asm("mov.b64 {%0,%1}, %2;" : "=f"(r.x), "=f"(r.y) : "l"(v));
    return r;
}

__device__ __forceinline__ int xbin(float x)
{
    int b = (int)((x - XMINF) * INVBW);
    return min(max(b, 0), NBINS - 1);
}

// ---------------------------------------------------------------------------
// midpoint-bilinear refine of mesh point r (row-major over RH x RW), batch n
// ---------------------------------------------------------------------------
__device__ __forceinline__ float4 refine_point(const float* __restrict__ verts,
                                               int n, int r)
{
    int i = r / RW, j = r % RW;
    int i0 = i >> 1, j0 = j >> 1;
    int oi = i & 1,  oj = j & 1;
    const float* base = verts + n * 3 * HH * WW;
    float vv[3];
    #pragma unroll
    for (int c = 0; c < 3; c++) {
        const float* pl = base + c * HH * WW;
        float v00 = pl[i0*WW + j0];
        float top = v00;
        if (oj) top = 0.5f * (v00 + pl[i0*WW + j0 + 1]);
        float val = top;
        if (oi) {
            float v10 = pl[(i0+1)*WW + j0];
            float bot = v10;
            if (oj) bot = 0.5f * (v10 + pl[(i0+1)*WW + j0 + 1]);
            val = 0.5f * (top + bot);
        }
        vv[c] = val;
    }
    return make_float4(vv[0], vv[1], vv[2],
                       0.5f*(vv[0]*vv[0] + vv[1]*vv[1] + vv[2]*vv[2]));
}

// ---------------------------------------------------------------------------
// K1: compute all points, histogram x-bins
// cb index: mesh batch n -> n ; pc batch n -> 2+n
// ---------------------------------------------------------------------------
__global__ void k1_prep_hist(const float* __restrict__ verts,
                             const float* __restrict__ pc)
{
    int idx = blockIdx.x * 256 + threadIdx.x;
    if (idx < NBQ_TOT) {
        int n = idx / QQ, r = idx % QQ;
        float4 p = refine_point(verts, n, r);
        g_ptsM[idx] = p;
        atomicAdd(&g_hist[n][xbin(p.x)], 1);
    } else if (idx < TOT_PTS) {
        int i2 = idx - NBQ_TOT;
        int n = i2 / P;
        const float* s = pc + (size_t)i2 * 3;
        float x = s[0], y = s[1], z = s[2];
        float4 p = make_float4(x, y, z, 0.5f*(x*x + y*y + z*z));
        g_ptsP[i2] = p;
        atomicAdd(&g_hist[2+n][xbin(x)], 1);
    }
}

// ---------------------------------------------------------------------------
// K2: sentinel-fill padded w array; per-cb prefix sums (padded + compact);
// init cursors; zero hist for next replay
// ---------------------------------------------------------------------------
__global__ void k2_prefix()
{
    int tid = threadIdx.x;
    float* nw = &g_bnw[0][0];
    for (int i = tid; i < 4*CAP; i += 256) nw[i] = -3.0e38f;
    __syncthreads();
    if (tid < 4) {
        int cb = tid, po = 0, co = 0;
        for (int k = 0; k < NBINS; k++) {
            int c = g_hist[cb][k];
            g_off[cb][k]  = po;
            g_cur[cb][k]  = po;
            g_ccur[cb][k] = co;
            po += (c + 3) & ~3;
            co += c;
            g_hist[cb][k] = 0;      // reset for next replay
        }
        g_off[cb][NBINS] = po;
    }
}

// ---------------------------------------------------------------------------
// K3: scatter points into bin-sorted arrays (padded b-copy + compact a-copy)
// ---------------------------------------------------------------------------
__global__ void k3_scatter()
{
    int idx = blockIdx.x * 256 + threadIdx.x;
    float4 p; int cb, loc;
    if (idx < NBQ_TOT) {
        int n = idx / QQ; loc = idx - n*QQ; p = g_ptsM[idx]; cb = n;
    } else if (idx < TOT_PTS) {
        int i2 = idx - NBQ_TOT;
        int n = i2 / P; loc = i2 - n*P; p = g_ptsP[i2]; cb = 2+n;
    } else return;
    int b = xbin(p.x);
    int pos = atomicAdd(&g_cur[cb][b], 1);
    g_bx[cb][pos] = p.x; g_by[cb][pos] = p.y;
    g_bz[cb][pos] = p.z; g_bnw[cb][pos] = -p.w;
    int cp = atomicAdd(&g_ccur[cb][b], 1);
    g_cx[cb][cp] = p.x; g_cy[cb][cp] = p.y;
    g_cz[cb][cp] = p.z; g_cw[cb][cp] = p.w;
    g_coid[cb][cp] = loc;
}

// ---------------------------------------------------------------------------
// K4: windowed chamfer (ring scan over x-bins, exact edge-bound termination)
//     + spin barrier + fused deterministic finalize
// ---------------------------------------------------------------------------
__global__ void __launch_bounds__(BLK) k4_chamfer(float* __restrict__ outp)
{
    __shared__ int   soff[NBINS+1];
    __shared__ float sh[4];
    __shared__ int   s_last;

    int bid = blockIdx.x, tid = threadIdx.x;
    int dirA = (bid < NB*CTA_A_PER);
    int n, chunk, cb_a, cb_b, nA;
    if (dirA) {
        n = bid / CTA_A_PER; chunk = bid % CTA_A_PER;
        cb_a = 2 + n; cb_b = n; nA = P;        // a = pc, b = mesh
    } else {
        int b2 = bid - NB*CTA_A_PER;
        n = b2 / CTA_B_PER; chunk = b2 % CTA_B_PER;
        cb_a = n; cb_b = 2 + n; nA = QQ;       // a = mesh, b = pc
    }
    for (int k = tid; k <= NBINS; k += BLK) soff[k] = g_off[cb_b][k];
    __syncthreads();

    int i = chunk * BLK + tid;
    int j = i < nA ? i : nA - 1;
    float ax = g_cx[cb_a][j], ay = g_cy[cb_a][j];
    float az = g_cz[cb_a][j], aw = g_cw[cb_a][j];
    int  oid = g_coid[cb_a][j];

    unsigned long long AX = pack2(ax, ax), AY = pack2(ay, ay), AZ = pack2(az, az);
    float ma = -3.0e38f, mb = -3.0e38f;

    const float* __restrict__ bx = g_bx[cb_b];
    const float* __restrict__ by = g_by[cb_b];
    const float* __restrict__ bz = g_bz[cb_b];
    const float* __restrict__ bw = g_bnw[cb_b];

    auto scan = [&](int k) {
        int s = soff[k], e = soff[k+1];
        for (int t = s; t < e; t += 4) {
            ulonglong2 X = *(const ulonglong2*)(bx + t);
            ulonglong2 Y = *(const ulonglong2*)(by + t);
            ulonglong2 Z = *(const ulonglong2*)(bz + t);
            ulonglong2 W = *(const ulonglong2*)(bw + t);
            unsigned long long v; float2 f;
            v = fma2(AZ, Z.x, W.x); v = fma2(AY, Y.x, v); v = fma2(AX, X.x, v);
            f = u2f(v); ma = fmaxf(ma, f.x); mb = fmaxf(mb, f.y);
            v = fma2(AZ, Z.y, W.y); v = fma2(AY, Y.y, v); v = fma2(AX, X.y, v);
            f = u2f(v); ma = fmaxf(ma, f.x); mb = fmaxf(mb, f.y);
        }
    };

    float xc = __shfl_sync(0xffffffffu, ax, 16);   // warp-uniform center
    int c = xbin(xc);
    scan(c);
    int lo = c, hi = c + 1;
    while (true) {
        float clo = (lo == 0)     ? -1.0e30f : XMINF + lo * BWF;
        float chi = (hi == NBINS) ?  1.0e30f : XMINF + hi * BWF;
        float m    = fmaxf(ma, mb);
        float need = 2.0f * (aw - m);
        float dl = fmaxf(ax - clo, 0.0f);
        float dr = fmaxf(chi - ax, 0.0f);
        int ok = (need <= dl*dl) && (need <= dr*dr);
        if (__all_sync(0xffffffffu, ok)) break;
        int canL = (lo > 0), canR = (hi < NBINS);
        if (!canL && !canR) break;
        int goL;
        if (!canL) goL = 0;
        else if (!canR) goL = 1;
        else goL = (xc - (XMINF + lo*BWF)) <= ((XMINF + hi*BWF) - xc);
        if (goL) { lo--; scan(lo); }
        else     { scan(hi); hi++; }
    }

    float mind = 2.0f * (aw - fmaxf(ma, mb));
    if (i < nA) {
        if (dirA) g_minA[n*P + oid]  = mind;
        else      g_minB[n*QQ + oid] = mind;
    }

    // ---- grid spin barrier (all 270 CTAs co-resident in wave 1) ----
    __threadfence();
    __syncthreads();
    if (tid == 0) {
        atomicAdd(&g_done, 1);
        while (*(volatile int*)&g_done < KGRID) { }
        __threadfence();
    }
    __syncthreads();

    // ---- deterministic finalize: fixed chunks by original index ----
    {
        int idx = bid * BLK + tid;
        float v = 0.0f;
        if (idx < NA_TOT)        v = g_minA[idx] * (1.0f/NA_TOT);
        else if (idx < TOT_PTS)  v = g_minB[idx - NA_TOT] * (1.0f/NBQ_TOT);
        #pragma unroll
        for (int o = 16; o > 0; o >>= 1) v += __shfl_down_sync(0xffffffffu, v, o);
        int lane = tid & 31, wid = tid >> 5;
        if (lane == 0) sh[wid] = v;
        __syncthreads();
        if (wid == 0) {
            v = (lane < 4) ? sh[lane] : 0.0f;
            #pragma unroll
            for (int o = 2; o > 0; o >>= 1) v += __shfl_down_sync(0xffffffffu, v, o);
            if (lane == 0) {
                g_fpart[bid] = v;
                __threadfence();
                int t = atomicAdd(&g_done2, 1);
                s_last = (t == KGRID - 1);
            }
        }
    }
    __syncthreads();
    if (s_last && tid == 0) {
        __threadfence();
        float r = 0.0f;
        #pragma unroll 1
        for (int k = 0; k < KGRID; k++) r += g_fpart[k];
        outp[0] = r;
        g_done = 0; g_done2 = 0;   // reset for next graph replay
    }
}

extern "C" void kernel_launch(void* const* d_in, const int* in_sizes, int n_in,
                              void* d_out, int out_size)
{
    // resolve inputs by size: vertices = 2*3*48*48 = 13824, pc = 2*8192*3 = 49152
    const float* verts = (const float*)d_in[0];
    const float* pc    = (const float*)d_in[1];
    if (n_in >= 2 && in_sizes[0] != NB*3*HH*WW) {
        verts = (const float*)d_in[1];
        pc    = (const float*)d_in[0];
    }

    int blocks = (TOT_PTS + 255) / 256;   // 135
    k1_prep_hist<<<blocks, 256>>>(verts, pc);
    k2_prefix<<<1, 256>>>();
    k3_scatter<<<blocks, 256>>>();
    k4_chamfer<<<KGRID, BLK>>>((float*)d_out);
}

// round 14
// speedup vs baseline: 2.5235x; 2.5235x over previous
#include <cuda_runtime.h>

#define NB 2
#define P  8192
#define HH 48
#define WW 48
#define RH 95
#define RW 95
#define QQ (RH*RW)          // 9025
#define NA_TOT (NB*P)       // 16384
#define NBQ_TOT (NB*QQ)     // 18050
#define TOT_PTS (NA_TOT + NBQ_TOT)  // 34434

#define NBINS 128
#define XMINF (-8.0f)
#define BWF   (0.125f)
#define INVBW (8.0f)
#define CAP   9600          // >= 9025 + 3*NBINS padding

#define BLK  128
#define SBIN 512            // smem bin-chunk (4 arrays x 512 x 4B = 8KB)
#define CTA_A_PER (P/BLK)            // 64
#define CTA_B_PER ((QQ+BLK-1)/BLK)   // 71
#define KGRID (NB*CTA_A_PER + NB*CTA_B_PER)  // 270

// scratch (allocation-free rule: __device__ globals; zero-init; self-resetting)
__device__ float4 g_ptsM[NBQ_TOT];
__device__ float4 g_ptsP[NA_TOT];
__device__ int    g_hist[4][NBINS];
__device__ int    g_off[4][NBINS+1];   // padded bin offsets (multiples of 4)
__device__ int    g_cur[4][NBINS];     // padded scatter cursors
__device__ int    g_ccur[4][NBINS];    // compact scatter cursors
__device__ __align__(16) float g_bx[4][CAP];
__device__ __align__(16) float g_by[4][CAP];
__device__ __align__(16) float g_bz[4][CAP];
__device__ __align__(16) float g_bnw[4][CAP];   // -0.5|b|^2 ; sentinel in pad slots
__device__ float g_cx[4][CAP];        // compact bin-sorted a-side copy
__device__ float g_cy[4][CAP];
__device__ float g_cz[4][CAP];
__device__ float g_cw[4][CAP];        // +0.5|a|^2
__device__ float g_fpart[KGRID];
__device__ int   g_done;

// ---------------------------------------------------------------------------
// f32x2 packed helpers
// ---------------------------------------------------------------------------
__device__ __forceinline__ unsigned long long fma2(unsigned long long a,
                                                   unsigned long long b,
                                                   unsigned long long c)
{
    unsigned long long d;
    asm("fma.rn.f32x2 %0, %1, %2, %3;" : "=l"(d) : "l"(a), "l"(b), "l"(c));
    return d;
}
__device__ __forceinline__ unsigned long long pack2(float x, float y)
{
    unsigned long long r;
    asm("mov.b64 %0, {%1,%2};" : "=l"(r) : "f"(x), "f"(y));
    return r;
}
__device__ __forceinline__ float2 u2f(unsigned long long v)
{
    float2 r;
    asm("mov.b64 {%0,%1}, %2;" : "=f"(r.x), "=f"(r.y) : "l"(v));
    return r;
}

__device__ __forceinline__ int xbin(float x)
{
    int b = (int)((x - XMINF) * INVBW);
    return min(max(b, 0), NBINS - 1);
}

// ---------------------------------------------------------------------------
// midpoint-bilinear refine of mesh point r (row-major over RH x RW), batch n
// ---------------------------------------------------------------------------
__device__ __forceinline__ float4 refine_point(const float* __restrict__ verts,
                                               int n, int r)
{
    int i = r / RW, j = r % RW;
    int i0 = i >> 1, j0 = j >> 1;
    int oi = i & 1,  oj = j & 1;
    const float* base = verts + n * 3 * HH * WW;
    float vv[3];
    #pragma unroll
    for (int c = 0; c < 3; c++) {
        const float* pl = base + c * HH * WW;
        float v00 = pl[i0*WW + j0];
        float top = v00;
        if (oj) top = 0.5f * (v00 + pl[i0*WW + j0 + 1]);
        float val = top;
        if (oi) {
            float v10 = pl[(i0+1)*WW + j0];
            float bot = v10;
            if (oj) bot = 0.5f * (v10 + pl[(i0+1)*WW + j0 + 1]);
            val = 0.5f * (top + bot);
        }
        vv[c] = val;
    }
    return make_float4(vv[0], vv[1], vv[2],
                       0.5f*(vv[0]*vv[0] + vv[1]*vv[1] + vv[2]*vv[2]));
}

// ---------------------------------------------------------------------------
// K1: compute all points, histogram x-bins (cb: mesh n -> n ; pc n -> 2+n)
// ---------------------------------------------------------------------------
__global__ void k1_prep_hist(const float* __restrict__ verts,
                             const float* __restrict__ pc)
{
    int idx = blockIdx.x * 256 + threadIdx.x;
    if (idx < NBQ_TOT) {
        int n = idx / QQ, r = idx % QQ;
        float4 p = refine_point(verts, n, r);
        g_ptsM[idx] = p;
        atomicAdd(&g_hist[n][xbin(p.x)], 1);
    } else if (idx < TOT_PTS) {
        int i2 = idx - NBQ_TOT;
        int n = i2 / P;
        const float* s = pc + (size_t)i2 * 3;
        float x = s[0], y = s[1], z = s[2];
        g_ptsP[i2] = make_float4(x, y, z, 0.5f*(x*x + y*y + z*z));
        atomicAdd(&g_hist[2+n][xbin(x)], 1);
    }
}

// ---------------------------------------------------------------------------
// K2: warp shfl-scan prefix sums (padded + compact), cursor init, targeted
// pad-slot sentinels, hist reset. 4 warps, one per cb.
// ---------------------------------------------------------------------------
__global__ void k2_prefix()
{
    int tid = threadIdx.x;
    int w = tid >> 5, l = tid & 31;
    if (w >= 4) return;
    int cb = w;
    int po = 0, co = 0;
    #pragma unroll
    for (int chunk = 0; chunk < 4; chunk++) {
        int k = chunk * 32 + l;
        int c  = g_hist[cb][k];
        int pa = (c + 3) & ~3;
        int ip = pa, ic = c;
        #pragma unroll
        for (int off = 1; off < 32; off <<= 1) {
            int tp = __shfl_up_sync(0xffffffffu, ip, off);
            int tc = __shfl_up_sync(0xffffffffu, ic, off);
            if (l >= off) { ip += tp; ic += tc; }
        }
        int excl_p = ip - pa + po;
        int excl_c = ic - c  + co;
        g_off[cb][k]  = excl_p;
        g_cur[cb][k]  = excl_p;
        g_ccur[cb][k] = excl_c;
        for (int q = c; q < pa; q++) g_bnw[cb][excl_p + q] = -3.0e38f;
        g_hist[cb][k] = 0;                 // reset for next replay
        po += __shfl_sync(0xffffffffu, ip, 31);
        co += __shfl_sync(0xffffffffu, ic, 31);
    }
    if (l == 0) g_off[cb][NBINS] = po;
}

// ---------------------------------------------------------------------------
// K3: scatter into bin-sorted arrays (padded b-copy + compact a-copy).
// Compact copy carries no original-index: mean is order-invariant up to fp
// rounding of the fixed reduction tree (per-thread order IS fixed).
// ---------------------------------------------------------------------------
__global__ void k3_scatter()
{
    int idx = blockIdx.x * 256 + threadIdx.x;
    float4 p; int cb;
    if (idx < NBQ_TOT) {
        int n = idx / QQ; p = g_ptsM[idx]; cb = n;
    } else if (idx < TOT_PTS) {
        int i2 = idx - NBQ_TOT;
        int n = i2 / P; p = g_ptsP[i2]; cb = 2+n;
    } else return;
    int b = xbin(p.x);
    int pos = atomicAdd(&g_cur[cb][b], 1);
    g_bx[cb][pos] = p.x; g_by[cb][pos] = p.y;
    g_bz[cb][pos] = p.z; g_bnw[cb][pos] = -p.w;
    int cp = atomicAdd(&g_ccur[cb][b], 1);
    g_cx[cb][cp] = p.x; g_cy[cb][cp] = p.y;
    g_cz[cb][cp] = p.z; g_cw[cb][cp] = p.w;
}

// ---------------------------------------------------------------------------
// K4: block-cooperative windowed chamfer. Each CTA owns 128 x-sorted
// a-points; rounds: fill one bin into smem (coalesced) -> all warps scan
// smem -> exact edge-bound vote. Last-done CTA reduces partials.
// ---------------------------------------------------------------------------
__global__ void __launch_bounds__(BLK) k4_chamfer(float* __restrict__ outp)
{
    __shared__ int   soff[NBINS+1];
    __shared__ __align__(16) float sx[SBIN];
    __shared__ __align__(16) float sy[SBIN];
    __shared__ __align__(16) float sz[SBIN];
    __shared__ __align__(16) float sw[SBIN];
    __shared__ float shred[4];
    __shared__ float s_axmin, s_axmax;
    __shared__ int   s_last;

    int bid = blockIdx.x, tid = threadIdx.x;
    int dirA = (bid < NB*CTA_A_PER);
    int n, chunk, cb_a, cb_b, nA;
    float wgt;
    if (dirA) {
        n = bid / CTA_A_PER; chunk = bid % CTA_A_PER;
        cb_a = 2 + n; cb_b = n; nA = P; wgt = 1.0f/NA_TOT;   // a=pc, b=mesh
    } else {
        int b2 = bid - NB*CTA_A_PER;
        n = b2 / CTA_B_PER; chunk = b2 % CTA_B_PER;
        cb_a = n; cb_b = 2 + n; nA = QQ; wgt = 1.0f/NBQ_TOT; // a=mesh, b=pc
    }
    for (int k = tid; k <= NBINS; k += BLK) soff[k] = g_off[cb_b][k];

    int i = chunk * BLK + tid;
    int j = i < nA ? i : nA - 1;
    float ax = g_cx[cb_a][j], ay = g_cy[cb_a][j];
    float az = g_cz[cb_a][j], aw = g_cw[cb_a][j];
    unsigned long long AX = pack2(ax, ax), AY = pack2(ay, ay), AZ = pack2(az, az);
    float ma = -3.0e38f, mb = -3.0e38f;

    // block-wide a-x extremes (for uniform expansion choice)
    {
        float mn = ax, mx = ax;
        #pragma unroll
        for (int o = 16; o > 0; o >>= 1) {
            mn = fminf(mn, __shfl_xor_sync(0xffffffffu, mn, o));
            mx = fmaxf(mx, __shfl_xor_sync(0xffffffffu, mx, o));
        }
        int lane = tid & 31, wid = tid >> 5;
        if (lane == 0) { shred[wid] = mn; }
        __syncthreads();
        if (tid == 0) {
            float m0 = fminf(fminf(shred[0], shred[1]), fminf(shred[2], shred[3]));
            s_axmin = m0;
        }
        __syncthreads();
        if (lane == 0) { shred[wid] = mx; }
        __syncthreads();
        if (tid == 0) {
            float m1 = fmaxf(fmaxf(shred[0], shred[1]), fmaxf(shred[2], shred[3]));
            s_axmax = m1;
        }
        __syncthreads();
    }

    const float* __restrict__ bx = g_bx[cb_b];
    const float* __restrict__ by = g_by[cb_b];
    const float* __restrict__ bz = g_bz[cb_b];
    const float* __restrict__ bw = g_bnw[cb_b];

    int c = xbin(0.5f * (s_axmin + s_axmax));
    int lo = c, hi = c;          // scanned bin range [lo, hi), initially empty

    while (true) {
        float clo = (lo == 0)     ? -1.0e30f : XMINF + lo * BWF;
        float chi = (hi == NBINS) ?  1.0e30f : XMINF + hi * BWF;
        float m    = fmaxf(ma, mb);
        float need = 2.0f * (aw - m);
        float dl = fmaxf(ax - clo, 0.0f);
        float dr = fmaxf(chi - ax, 0.0f);
        int ok = (hi > lo) && (need <= dl*dl) && (need <= dr*dr);
        if (__syncthreads_and(ok)) break;
        int canL = (lo > 0), canR = (hi < NBINS);
        if (!canL && !canR) break;
        int goL;
        if (!canL) goL = 0;
        else if (!canR) goL = 1;
        else goL = (s_axmin - (XMINF + lo*BWF)) <= ((XMINF + hi*BWF) - s_axmax);
        int k;
        if (goL) {               // bulk-skip empty bins leftward
            k = lo - 1;
            while (k > 0 && soff[k+1] == soff[k]) k--;
            lo = k;
        } else {                 // bulk-skip empty bins rightward
            k = hi;
            while (k < NBINS-1 && soff[k+1] == soff[k]) k++;
            hi = k + 1;
        }
        // scan bin k: smem chunks, all warps over all points
        for (int s0 = soff[k]; s0 < soff[k+1]; s0 += SBIN) {
            int m2 = min(soff[k+1] - s0, SBIN);
            __syncthreads();
            for (int t = tid; t < m2; t += BLK) {
                sx[t] = bx[s0+t]; sy[t] = by[s0+t];
                sz[t] = bz[s0+t]; sw[t] = bw[s0+t];
            }
            __syncthreads();
            for (int t = 0; t < m2; t += 4) {
                ulonglong2 X = *(const ulonglong2*)(sx + t);
                ulonglong2 Y = *(const ulonglong2*)(sy + t);
                ulonglong2 Z = *(const ulonglong2*)(sz + t);
                ulonglong2 W = *(const ulonglong2*)(sw + t);
                unsigned long long v; float2 f;
                v = fma2(AZ, Z.x, W.x); v = fma2(AY, Y.x, v); v = fma2(AX, X.x, v);
                f = u2f(v); ma = fmaxf(ma, f.x); mb = fmaxf(mb, f.y);
                v = fma2(AZ, Z.y, W.y); v = fma2(AY, Y.y, v); v = fma2(AX, X.y, v);
                f = u2f(v); ma = fmaxf(ma, f.x); mb = fmaxf(mb, f.y);
            }
        }
    }

    // per-CTA weighted partial sum (fixed-order reduction tree)
    float mind = 2.0f * (aw - fmaxf(ma, mb));
    float v = (i < nA) ? mind * wgt : 0.0f;
    #pragma unroll
    for (int o = 16; o > 0; o >>= 1) v += __shfl_down_sync(0xffffffffu, v, o);
    int lane = tid & 31, wid = tid >> 5;
    __syncthreads();
    if (lane == 0) shred[wid] = v;
    __syncthreads();
    if (tid == 0) {
        g_fpart[bid] = (shred[0] + shred[1]) + (shred[2] + shred[3]);
        __threadfence();
        int t = atomicAdd(&g_done, 1);
        s_last = (t == KGRID - 1);
    }
    __syncthreads();

    // last-done CTA: deterministic fixed-order final sum (warp 0)
    if (s_last && tid < 32) {
        __threadfence();
        float r = 0.0f;
        for (int q = tid; q < KGRID; q += 32) r += g_fpart[q];
        #pragma unroll
        for (int o = 16; o > 0; o >>= 1) r += __shfl_down_sync(0xffffffffu, r, o);
        if (tid == 0) { outp[0] = r; g_done = 0; }
    }
}

extern "C" void kernel_launch(void* const* d_in, const int* in_sizes, int n_in,
                              void* d_out, int out_size)
{
    // resolve inputs by size: vertices = 2*3*48*48 = 13824, pc = 2*8192*3 = 49152
    const float* verts = (const float*)d_in[0];
    const float* pc    = (const float*)d_in[1];
    if (n_in >= 2 && in_sizes[0] != NB*3*HH*WW) {
        verts = (const float*)d_in[1];
        pc    = (const float*)d_in[0];
    }

    int blocks = (TOT_PTS + 255) / 256;   // 135
    k1_prep_hist<<<blocks, 256>>>(verts, pc);
    k2_prefix<<<1, 128>>>();
    k3_scatter<<<blocks, 256>>>();
    k4_chamfer<<<KGRID, BLK>>>((float*)d_out);
}

// round 16
// speedup vs baseline: 7.5124x; 2.9770x over previous
#include <cuda_runtime.h>

typedef unsigned long long ull;

#define NB 2
#define P  8192
#define HH 48
#define WW 48
#define RH 95
#define RW 95
#define QQ (RH*RW)            // 9025
#define QPAD 9216             // cols padded to CC*1024
#define ROWS_CTA 256          // 32 lanes x RPT
#define RPT 8
#define COLS_CTA 1024         // 8 warps x 128
#define WARPS 8
#define BLK 256
#define RC (P/ROWS_CTA)       // 32 row chunks per batch
#define CC (QPAD/COLS_CTA)    // 9  col chunks per batch
#define GRID (NB*RC*CC)       // 576
#define NROWP (NB*RC)         // 64 row partials
#define NCOLP (NB*CC)         // 18 col partials
#define NPART (NROWP+NCOLP)   // 82

// scratch (allocation-free rule: __device__ globals; zero-init; self-resetting)
__device__ __align__(16) float g_rx[NB*P], g_ry[NB*P], g_rz[NB*P], g_rka[NB*P];   // rka=0.5|a|^2
__device__ __align__(16) float g_mx[NB*QPAD], g_my[NB*QPAD], g_mz[NB*QPAD], g_mkb[NB*QPAD]; // mkb=-0.5|b|^2
__device__ float g_rowmax[CC][NB*P];
__device__ float g_colmax[RC][NB*QPAD];
__device__ float g_part[NPART];
__device__ int   g_rowcnt[NB*RC], g_colcnt[NB*CC], g_done;

// ---------------------------------------------------------------------------
// f32x2 packed helpers
// ---------------------------------------------------------------------------
__device__ __forceinline__ ull fma2(ull a, ull b, ull c)
{
    ull d;
    asm("fma.rn.f32x2 %0, %1, %2, %3;" : "=l"(d) : "l"(a), "l"(b), "l"(c));
    return d;
}
__device__ __forceinline__ ull add2(ull a, ull b)
{
    ull d;
    asm("add.rn.f32x2 %0, %1, %2;" : "=l"(d) : "l"(a), "l"(b));
    return d;
}
__device__ __forceinline__ ull pack2(float x, float y)
{
    ull r;
    asm("mov.b64 %0, {%1,%2};" : "=l"(r) : "f"(x), "f"(y));
    return r;
}
__device__ __forceinline__ float2 u2f(ull v)
{
    float2 r;
    asm("mov.b64 {%0,%1}, %2;" : "=f"(r.x), "=f"(r.y) : "l"(v));
    return r;
}

// ---------------------------------------------------------------------------
// midpoint-bilinear refine of mesh point r (row-major over RH x RW), batch n
// ---------------------------------------------------------------------------
__device__ __forceinline__ float4 refine_point(const float* __restrict__ verts,
                                               int n, int r)
{
    int i = r / RW, j = r % RW;
    int i0 = i >> 1, j0 = j >> 1;
    int oi = i & 1,  oj = j & 1;
    const float* base = verts + n * 3 * HH * WW;
    float vv[3];
    #pragma unroll
    for (int c = 0; c < 3; c++) {
        const float* pl = base + c * HH * WW;
        float v00 = pl[i0*WW + j0];
        float top = v00;
        if (oj) top = 0.5f * (v00 + pl[i0*WW + j0 + 1]);
        float val = top;
        if (oi) {
            float v10 = pl[(i0+1)*WW + j0];
            float bot = v10;
            if (oj) bot = 0.5f * (v10 + pl[(i0+1)*WW + j0 + 1]);
            val = 0.5f * (top + bot);
        }
        vv[c] = val;
    }
    return make_float4(vv[0], vv[1], vv[2],
                       0.5f*(vv[0]*vv[0] + vv[1]*vv[1] + vv[2]*vv[2]));
}

// ---------------------------------------------------------------------------
// prep: SoA arrays. rows = pc, cols = refined mesh (sentinel-padded)
// ---------------------------------------------------------------------------
__global__ void prep_kernel(const float* __restrict__ verts,
                            const float* __restrict__ pc)
{
    int idx = blockIdx.x * 256 + threadIdx.x;
    if (idx < NB*QPAD) {
        int n = idx / QPAD, q = idx % QPAD;
        if (q < QQ) {
            float4 b = refine_point(verts, n, q);
            g_mx[idx] = b.x; g_my[idx] = b.y; g_mz[idx] = b.z; g_mkb[idx] = -b.w;
        } else {
            g_mx[idx] = 0.0f; g_my[idx] = 0.0f; g_mz[idx] = 0.0f; g_mkb[idx] = -3.0e38f;
        }
    } else {
        int i2 = idx - NB*QPAD;
        if (i2 < NB*P) {
            const float* s = pc + (size_t)i2 * 3;
            float x = s[0], y = s[1], z = s[2];
            g_rx[i2] = x; g_ry[i2] = y; g_rz[i2] = z;
            g_rka[i2] = 0.5f*(x*x + y*y + z*z);
        }
    }
}

// ---------------------------------------------------------------------------
// block sum reduce over BLK=256 (fixed tree -> deterministic); result in tid 0
// ---------------------------------------------------------------------------
__device__ __forceinline__ float block_sum(float v, float* sp)
{
    #pragma unroll
    for (int o = 16; o > 0; o >>= 1) v += __shfl_down_sync(0xffffffffu, v, o);
    int lane = threadIdx.x & 31, w = threadIdx.x >> 5;
    if (lane == 0) sp[w] = v;
    __syncthreads();
    if (w == 0) {
        v = (lane < WARPS) ? sp[lane] : 0.0f;
        #pragma unroll
        for (int o = 4; o > 0; o >>= 1) v += __shfl_down_sync(0xffffffffu, v, o);
    }
    __syncthreads();
    return v;
}

// ---------------------------------------------------------------------------
// main: shared-matrix chamfer via systolic rotation.
//   s  = a.b - 0.5|b|^2   (3-FFMA2 chain, init = rotating Kb)  -> row max
//   v  = s - 0.5|a|^2     (1 ADD2)                             -> col max
// row min_d = 2*(0.5|a|^2 - max_b s) ; col min_d = -2*max_a v
// Each lane: 8 rows (registers) x rotating packed b-pair. Col-max travels
// with its b. Hierarchical deterministic finalize.
// ---------------------------------------------------------------------------
__global__ void __launch_bounds__(BLK, 2) kmain(float* __restrict__ outp)
{
    __shared__ float srm[WARPS][ROWS_CTA];   // 8KB: per-warp row maxes
    __shared__ float sp[WARPS];
    __shared__ int   s_rl, s_cl, s_fin;

    int bid = blockIdx.x, tid = threadIdx.x;
    int w = tid >> 5, l = tid & 31;
    int n  = bid / (RC*CC);
    int rem = bid % (RC*CC);
    int rc = rem / CC, cc = rem % CC;

    // ---- load 8 rows into registers ----
    ull AX[RPT], AY[RPT], AZ[RPT], KA[RPT];
    float rmA[RPT], rmB[RPT];
    int rbase = n*P + rc*ROWS_CTA;
    #pragma unroll
    for (int r = 0; r < RPT; r++) {
        int row = rbase + r*32 + l;
        float x = g_rx[row], y = g_ry[row], z = g_rz[row], ka = g_rka[row];
        AX[r] = pack2(x, x); AY[r] = pack2(y, y); AZ[r] = pack2(z, z);
        KA[r] = pack2(-ka, -ka);
        rmA[r] = -3.0e38f; rmB[r] = -3.0e38f;
    }

    // ---- two rotation blocks of 64 cols per warp ----
    int cwbase = n*QPAD + cc*COLS_CTA + w*128;
    #pragma unroll 1
    for (int blk = 0; blk < 2; blk++) {
        int b0 = cwbase + blk*64;
        ull BX = *(const ull*)(g_mx  + b0 + 2*l);
        ull BY = *(const ull*)(g_my  + b0 + 2*l);
        ull BZ = *(const ull*)(g_mz  + b0 + 2*l);
        ull KB = *(const ull*)(g_mkb + b0 + 2*l);
        float cmx = -3.0e38f, cmy = -3.0e38f;

        #pragma unroll 1
        for (int step = 0; step < 32; step++) {
            // prefetch next rotation (hide shfl latency behind compute)
            int src = (l + 1) & 31;
            ull nBX = __shfl_sync(0xffffffffu, BX, src);
            ull nBY = __shfl_sync(0xffffffffu, BY, src);
            ull nBZ = __shfl_sync(0xffffffffu, BZ, src);
            ull nKB = __shfl_sync(0xffffffffu, KB, src);
            #pragma unroll
            for (int r = 0; r < RPT; r++) {
                ull s = fma2(AZ[r], BZ, KB);
                s = fma2(AY[r], BY, s);
                s = fma2(AX[r], BX, s);
                float2 f = u2f(s);
                rmA[r] = fmaxf(rmA[r], f.x);
                rmB[r] = fmaxf(rmB[r], f.y);
                ull v = add2(s, KA[r]);
                float2 g = u2f(v);
                cmx = fmaxf(cmx, g.x);
                cmy = fmaxf(cmy, g.y);
            }
            BX = nBX; BY = nBY; BZ = nBZ; KB = nKB;
            float t0 = __shfl_sync(0xffffffffu, cmx, src);
            float t1 = __shfl_sync(0xffffffffu, cmy, src);
            cmx = t0; cmy = t1;
        }
        // after 32 steps b-pair (and its traveling colmax) is home
        g_colmax[rc][b0 + 2*l]     = cmx;
        g_colmax[rc][b0 + 2*l + 1] = cmy;
    }

    // ---- combine row maxes across warps ----
    #pragma unroll
    for (int r = 0; r < RPT; r++)
        srm[w][r*32 + l] = fmaxf(rmA[r], rmB[r]);
    __syncthreads();
    {
        float rv = srm[0][tid];
        #pragma unroll
        for (int ww = 1; ww < WARPS; ww++) rv = fmaxf(rv, srm[ww][tid]);
        g_rowmax[cc][rbase + tid] = rv;
    }

    // ---- group arrivals ----
    __threadfence();
    __syncthreads();
    if (tid == 0) {
        s_rl = (atomicAdd(&g_rowcnt[n*RC + rc], 1) == CC - 1);
        s_cl = (atomicAdd(&g_colcnt[n*CC + cc], 1) == RC - 1);
    }
    __syncthreads();

    int narr = 0;
    if (s_rl) {     // row finalize for (n, rc): 256 rows, combine CC splits
        __threadfence();
        int row = rbase + tid;
        float m = g_rowmax[0][row];
        #pragma unroll
        for (int c = 1; c < CC; c++) m = fmaxf(m, g_rowmax[c][row]);
        float v = 2.0f * (g_rka[row] - m) * (1.0f/(NB*P));
        float s = block_sum(v, sp);
        if (tid == 0) {
            g_part[n*RC + rc] = s;
            g_rowcnt[n*RC + rc] = 0;      // reset for next graph replay
            narr++;
        }
    }
    if (s_cl) {     // col finalize for (n, cc): 1024 cols, combine RC splits
        __threadfence();
        float v = 0.0f;
        #pragma unroll 1
        for (int k = tid; k < COLS_CTA; k += BLK) {
            int col = cc*COLS_CTA + k;
            if (col < QQ) {
                int ci = n*QPAD + col;
                float m = g_colmax[0][ci];
                #pragma unroll
                for (int rr = 1; rr < RC; rr++) m = fmaxf(m, g_colmax[rr][ci]);
                // min_a d = -2*m  (0.5|b|^2 already inside the traveling max)
                v += -2.0f * m * (1.0f/(NB*QQ));
            }
        }
        float s = block_sum(v, sp);
        if (tid == 0) {
            g_part[NROWP + n*CC + cc] = s;
            g_colcnt[n*CC + cc] = 0;      // reset for next graph replay
            narr++;
        }
    }

    // ---- global last-arrival: fixed-order sum of 82 partials ----
    if (tid == 0) {
        s_fin = 0;
        if (narr) {
            __threadfence();
            int t = atomicAdd(&g_done, narr);
            if (t + narr == NPART) s_fin = 1;
        }
    }
    __syncthreads();
    if (s_fin && tid == 0) {
        __threadfence();
        float r = 0.0f;
        #pragma unroll 1
        for (int k = 0; k < NPART; k++) r += g_part[k];
        outp[0] = r;
        g_done = 0;                       // reset for next graph replay
    }
}

extern "C" void kernel_launch(void* const* d_in, const int* in_sizes, int n_in,
                              void* d_out, int out_size)
{
    // resolve inputs by size: vertices = 2*3*48*48 = 13824, pc = 2*8192*3 = 49152
    const float* verts = (const float*)d_in[0];
    const float* pc    = (const float*)d_in[1];
    if (n_in >= 2 && in_sizes[0] != NB*3*HH*WW) {
        verts = (const float*)d_in[1];
        pc    = (const float*)d_in[0];
    }

    int prep_items = NB*QPAD + NB*P;      // 34816
    prep_kernel<<<(prep_items + 255)/256, 256>>>(verts, pc);
    kmain<<<GRID, BLK>>>((float*)d_out);
}

// round 17
// speedup vs baseline: 7.5594x; 1.0063x over previous
#include <cuda_runtime.h>

typedef unsigned long long ull;

#define NB 2
#define P  8192
#define HH 48
#define WW 48
#define RH 95
#define RW 95
#define QQ (RH*RW)            // 9025
#define QPAD 9216             // cols padded to CC*1024
#define ROWS_CTA 256          // 32 lanes x RPT
#define RPT 8
#define COLS_CTA 1024         // 8 warps x 128
#define WARPS 8
#define BLK 256
#define RC (P/ROWS_CTA)       // 32 row chunks per batch
#define CC (QPAD/COLS_CTA)    // 9  col chunks per batch
#define GRID (NB*RC*CC)       // 576
#define NROWP (NB*RC)         // 64 row partials
#define NCOLP (NB*CC)         // 18 col partials
#define NPART (NROWP+NCOLP)   // 82

// scratch (allocation-free rule: __device__ globals; zero-init; self-resetting)
__device__ __align__(16) float g_rx[NB*P], g_ry[NB*P], g_rz[NB*P], g_rka[NB*P];   // rka=0.5|a|^2
__device__ __align__(16) float g_mx[NB*QPAD], g_my[NB*QPAD], g_mz[NB*QPAD], g_mkb[NB*QPAD]; // mkb=-0.5|b|^2
__device__ float g_rowmax[CC][NB*P];
__device__ float g_colmax[RC][NB*QPAD];
__device__ float g_part[NPART];
__device__ int   g_rowcnt[NB*RC], g_colcnt[NB*CC], g_done;

// ---------------------------------------------------------------------------
// f32x2 packed helpers
// ---------------------------------------------------------------------------
__device__ __forceinline__ ull fma2(ull a, ull b, ull c)
{
    ull d;
    asm("fma.rn.f32x2 %0, %1, %2, %3;" : "=l"(d) : "l"(a), "l"(b), "l"(c));
    return d;
}
__device__ __forceinline__ ull add2(ull a, ull b)
{
    ull d;
    asm("add.rn.f32x2 %0, %1, %2;" : "=l"(d) : "l"(a), "l"(b));
    return d;
}
__device__ __forceinline__ ull pack2(float x, float y)
{
    ull r;
    asm("mov.b64 %0, {%1,%2};" : "=l"(r) : "f"(x), "f"(y));
    return r;
}
__device__ __forceinline__ float2 u2f(ull v)
{
    float2 r;
    asm("mov.b64 {%0,%1}, %2;" : "=f"(r.x), "=f"(r.y) : "l"(v));
    return r;
}

// ---------------------------------------------------------------------------
// midpoint-bilinear refine of mesh point r (row-major over RH x RW), batch n
// ---------------------------------------------------------------------------
__device__ __forceinline__ float4 refine_point(const float* __restrict__ verts,
                                               int n, int r)
{
    int i = r / RW, j = r % RW;
    int i0 = i >> 1, j0 = j >> 1;
    int oi = i & 1,  oj = j & 1;
    const float* base = verts + n * 3 * HH * WW;
    float vv[3];
    #pragma unroll
    for (int c = 0; c < 3; c++) {
        const float* pl = base + c * HH * WW;
        float v00 = pl[i0*WW + j0];
        float top = v00;
        if (oj) top = 0.5f * (v00 + pl[i0*WW + j0 + 1]);
        float val = top;
        if (oi) {
            float v10 = pl[(i0+1)*WW + j0];
            float bot = v10;
            if (oj) bot = 0.5f * (v10 + pl[(i0+1)*WW + j0 + 1]);
            val = 0.5f * (top + bot);
        }
        vv[c] = val;
    }
    return make_float4(vv[0], vv[1], vv[2],
                       0.5f*(vv[0]*vv[0] + vv[1]*vv[1] + vv[2]*vv[2]));
}

// ---------------------------------------------------------------------------
// prep: SoA arrays. rows = pc, cols = refined mesh (sentinel-padded)
// ---------------------------------------------------------------------------
__global__ void prep_kernel(const float* __restrict__ verts,
                            const float* __restrict__ pc)
{
    int idx = blockIdx.x * 256 + threadIdx.x;
    if (idx < NB*QPAD) {
        int n = idx / QPAD, q = idx % QPAD;
        if (q < QQ) {
            float4 b = refine_point(verts, n, q);
            g_mx[idx] = b.x; g_my[idx] = b.y; g_mz[idx] = b.z; g_mkb[idx] = -b.w;
        } else {
            g_mx[idx] = 0.0f; g_my[idx] = 0.0f; g_mz[idx] = 0.0f; g_mkb[idx] = -3.0e38f;
        }
    } else {
        int i2 = idx - NB*QPAD;
        if (i2 < NB*P) {
            const float* s = pc + (size_t)i2 * 3;
            float x = s[0], y = s[1], z = s[2];
            g_rx[i2] = x; g_ry[i2] = y; g_rz[i2] = z;
            g_rka[i2] = 0.5f*(x*x + y*y + z*z);
        }
    }
}

// ---------------------------------------------------------------------------
// block sum reduce over BLK=256 (fixed tree -> deterministic); result in tid 0
// ---------------------------------------------------------------------------
__device__ __forceinline__ float block_sum(float v, float* sp)
{
    #pragma unroll
    for (int o = 16; o > 0; o >>= 1) v += __shfl_down_sync(0xffffffffu, v, o);
    int lane = threadIdx.x & 31, w = threadIdx.x >> 5;
    if (lane == 0) sp[w] = v;
    __syncthreads();
    if (w == 0) {
        v = (lane < WARPS) ? sp[lane] : 0.0f;
        #pragma unroll
        for (int o = 4; o > 0; o >>= 1) v += __shfl_down_sync(0xffffffffu, v, o);
    }
    __syncthreads();
    return v;
}

// ---------------------------------------------------------------------------
// one systolic substep: compute 8 rows vs resident b-pair, tree-reduced
// col contribution folded into traveling cm, then consume prefetched regs.
// ---------------------------------------------------------------------------
#define SUBSTEP(BX_, BY_, BZ_, KB_, CM_)                                      \
    {                                                                         \
        float vx[RPT], vy[RPT];                                               \
        _Pragma("unroll")                                                     \
        for (int r = 0; r < RPT; r++) {                                       \
            ull s = fma2(AZ[r], BZ_, KB_);                                    \
            s = fma2(AY[r], BY_, s);                                          \
            s = fma2(AX[r], BX_, s);                                          \
            float2 f = u2f(s);                                                \
            rmA[r] = fmaxf(rmA[r], f.x);                                      \
            rmB[r] = fmaxf(rmB[r], f.y);                                      \
            ull v = add2(s, KA[r]);                                           \
            float2 g = u2f(v);                                                \
            vx[r] = g.x; vy[r] = g.y;                                         \
        }                                                                     \
        /* depth-3 tree then single fold into traveling colmax */             \
        float tx0 = fmaxf(vx[0], vx[1]), tx1 = fmaxf(vx[2], vx[3]);           \
        float tx2 = fmaxf(vx[4], vx[5]), tx3 = fmaxf(vx[6], vx[7]);           \
        float ty0 = fmaxf(vy[0], vy[1]), ty1 = fmaxf(vy[2], vy[3]);           \
        float ty2 = fmaxf(vy[4], vy[5]), ty3 = fmaxf(vy[6], vy[7]);           \
        float txa = fmaxf(tx0, tx1), txb = fmaxf(tx2, tx3);                   \
        float tya = fmaxf(ty0, ty1), tyb = fmaxf(ty2, ty3);                   \
        float2 cmf = u2f(CM_);                                                \
        cmf.x = fmaxf(cmf.x, fmaxf(txa, txb));                                \
        cmf.y = fmaxf(cmf.y, fmaxf(tya, tyb));                                \
        CM_ = pack2(cmf.x, cmf.y);                                            \
    }

// ---------------------------------------------------------------------------
// main: shared-matrix chamfer via systolic rotation (double-buffered, x2).
//   s  = a.b - 0.5|b|^2   (3-FFMA2 chain, init = rotating Kb)  -> row max
//   v  = s - 0.5|a|^2     (1 ADD2)                             -> col max
// row min_d = 2*(0.5|a|^2 - max_b s) ; col min_d = -2*max_a v
// ---------------------------------------------------------------------------
__global__ void __launch_bounds__(BLK, 2) kmain(float* __restrict__ outp)
{
    __shared__ float srm[WARPS][ROWS_CTA];   // 8KB: per-warp row maxes
    __shared__ float sp[WARPS];
    __shared__ int   s_rl, s_cl, s_fin;

    int bid = blockIdx.x, tid = threadIdx.x;
    int w = tid >> 5, l = tid & 31;
    int n  = bid / (RC*CC);
    int rem = bid % (RC*CC);
    int rc = rem / CC, cc = rem % CC;

    // ---- load 8 rows into registers ----
    ull AX[RPT], AY[RPT], AZ[RPT], KA[RPT];
    float rmA[RPT], rmB[RPT];
    int rbase = n*P + rc*ROWS_CTA;
    #pragma unroll
    for (int r = 0; r < RPT; r++) {
        int row = rbase + r*32 + l;
        float x = g_rx[row], y = g_ry[row], z = g_rz[row], ka = g_rka[row];
        AX[r] = pack2(x, x); AY[r] = pack2(y, y); AZ[r] = pack2(z, z);
        KA[r] = pack2(-ka, -ka);
        rmA[r] = -3.0e38f; rmB[r] = -3.0e38f;
    }

    int src = (l + 1) & 31;

    // ---- two rotation blocks of 64 cols per warp ----
    int cwbase = n*QPAD + cc*COLS_CTA + w*128;
    #pragma unroll 1
    for (int blk = 0; blk < 2; blk++) {
        int b0 = cwbase + blk*64;
        ull BX0 = *(const ull*)(g_mx  + b0 + 2*l);
        ull BY0 = *(const ull*)(g_my  + b0 + 2*l);
        ull BZ0 = *(const ull*)(g_mz  + b0 + 2*l);
        ull KB0 = *(const ull*)(g_mkb + b0 + 2*l);
        ull CM0 = pack2(-3.0e38f, -3.0e38f);
        ull BX1, BY1, BZ1, KB1, CM1;

        #pragma unroll 1
        for (int step = 0; step < 32; step += 2) {
            // buffer 0 -> prefetch into buffer 1
            BX1 = __shfl_sync(0xffffffffu, BX0, src);
            BY1 = __shfl_sync(0xffffffffu, BY0, src);
            BZ1 = __shfl_sync(0xffffffffu, BZ0, src);
            KB1 = __shfl_sync(0xffffffffu, KB0, src);
            SUBSTEP(BX0, BY0, BZ0, KB0, CM0)
            CM1 = __shfl_sync(0xffffffffu, CM0, src);
            // buffer 1 -> prefetch into buffer 0
            BX0 = __shfl_sync(0xffffffffu, BX1, src);
            BY0 = __shfl_sync(0xffffffffu, BY1, src);
            BZ0 = __shfl_sync(0xffffffffu, BZ1, src);
            KB0 = __shfl_sync(0xffffffffu, KB1, src);
            SUBSTEP(BX1, BY1, BZ1, KB1, CM1)
            CM0 = __shfl_sync(0xffffffffu, CM1, src);
        }
        // after 32 rotations the b-pair (and its traveling colmax) is home
        float2 cmf = u2f(CM0);
        g_colmax[rc][b0 + 2*l]     = cmf.x;
        g_colmax[rc][b0 + 2*l + 1] = cmf.y;
    }

    // ---- combine row maxes across warps ----
    #pragma unroll
    for (int r = 0; r < RPT; r++)
        srm[w][r*32 + l] = fmaxf(rmA[r], rmB[r]);
    __syncthreads();
    {
        float rv = srm[0][tid];
        #pragma unroll
        for (int ww = 1; ww < WARPS; ww++) rv = fmaxf(rv, srm[ww][tid]);
        g_rowmax[cc][rbase + tid] = rv;
    }

    // ---- group arrivals ----
    __threadfence();
    __syncthreads();
    if (tid == 0) {
        s_rl = (atomicAdd(&g_rowcnt[n*RC + rc], 1) == CC - 1);
        s_cl = (atomicAdd(&g_colcnt[n*CC + cc], 1) == RC - 1);
    }
    __syncthreads();

    int narr = 0;
    if (s_rl) {     // row finalize for (n, rc): 256 rows, combine CC splits
        __threadfence();
        int row = rbase + tid;
        float m = g_rowmax[0][row];
        #pragma unroll
        for (int c = 1; c < CC; c++) m = fmaxf(m, g_rowmax[c][row]);
        float v = 2.0f * (g_rka[row] - m) * (1.0f/(NB*P));
        float s = block_sum(v, sp);
        if (tid == 0) {
            g_part[n*RC + rc] = s;
            g_rowcnt[n*RC + rc] = 0;      // reset for next graph replay
            narr++;
        }
    }
    if (s_cl) {     // col finalize for (n, cc): 1024 cols, combine RC splits
        __threadfence();
        float v = 0.0f;
        #pragma unroll 1
        for (int k = tid; k < COLS_CTA; k += BLK) {
            int col = cc*COLS_CTA + k;
            if (col < QQ) {
                int ci = n*QPAD + col;
                float m = g_colmax[0][ci];
                #pragma unroll
                for (int rr = 1; rr < RC; rr++) m = fmaxf(m, g_colmax[rr][ci]);
                // min_a d = -2*m  (0.5|b|^2 already inside the traveling max)
                v += -2.0f * m * (1.0f/(NB*QQ));
            }
        }
        float s = block_sum(v, sp);
        if (tid == 0) {
            g_part[NROWP + n*CC + cc] = s;
            g_colcnt[n*CC + cc] = 0;      // reset for next graph replay
            narr++;
        }
    }

    // ---- global last-arrival: fixed-order sum of 82 partials ----
    if (tid == 0) {
        s_fin = 0;
        if (narr) {
            __threadfence();
            int t = atomicAdd(&g_done, narr);
            if (t + narr == NPART) s_fin = 1;
        }
    }
    __syncthreads();
    if (s_fin && tid == 0) {
        __threadfence();
        float r = 0.0f;
        #pragma unroll 1
        for (int k = 0; k < NPART; k++) r += g_part[k];
        outp[0] = r;
        g_done = 0;                       // reset for next graph replay
    }
}

extern "C" void kernel_launch(void* const* d_in, const int* in_sizes, int n_in,
                              void* d_out, int out_size)
{
    // resolve inputs by size: vertices = 2*3*48*48 = 13824, pc = 2*8192*3 = 49152
    const float* verts = (const float*)d_in[0];
    const float* pc    = (const float*)d_in[1];
    if (n_in >= 2 && in_sizes[0] != NB*3*HH*WW) {
        verts = (const float*)d_in[1];
        pc    = (const float*)d_in[0];
    }

    int prep_items = NB*QPAD + NB*P;      // 34816
    prep_kernel<<<(prep_items + 255)/256, 256>>>(verts, pc);
    kmain<<<GRID, BLK>>>((float*)d_out);
}